// round 16
// baseline (speedup 1.0000x reference)
#include <cuda_runtime.h>
#include <cstdint>

#define DMODEL     1024
#define NEXP       8
#define TOKENS_TOT 32768
#define TPB        128
#define WARPS      4            // per CTA
#define TPW        16           // tokens per warp
#define TPG        4            // tokens per group (inner batch)
#define NGRP       (TPW / TPG)  // 4
#define NCHUNK     (NGRP * 8)   // 32 flat chunks per warp
#define NBLOCKS    (TOKENS_TOT / (WARPS * TPW))   // 512

typedef unsigned long long ull;

// ---------- packed fp32x2 FMA (sm_103a) ----------
__device__ __forceinline__ ull ffma2(ull a, ull b, ull c) {
    ull d;
    asm("fma.rn.f32x2 %0, %1, %2, %3;" : "=l"(d) : "l"(a), "l"(b), "l"(c));
    return d;
}
__device__ __forceinline__ void unpack2(ull v, float& lo, float& hi) {
    asm("mov.b64 {%0, %1}, %2;" : "=f"(lo), "=f"(hi) : "l"(v));
}

// ---------- integer warp redux (f32 redux does NOT exist on sm_103) ----------
__device__ __forceinline__ unsigned redux_max_u32(unsigned v) {
    unsigned r;
    asm volatile("redux.sync.max.u32 %0, %1, 0xffffffff;" : "=r"(r) : "r"(v));
    return r;
}
__device__ __forceinline__ unsigned redux_min_u32(unsigned v) {
    unsigned r;
    asm volatile("redux.sync.min.u32 %0, %1, 0xffffffff;" : "=r"(r) : "r"(v));
    return r;
}

// Order-preserving float <-> u32 total-order map: u32 max == float max.
__device__ __forceinline__ unsigned fmono(float v) {
    unsigned u = __float_as_uint(v);
    return ((int)u < 0) ? ~u : (u ^ 0x80000000u);
}
__device__ __forceinline__ float fmono_inv(unsigned k) {
    return __uint_as_float(((int)k < 0) ? (k ^ 0x80000000u) : ~k);
}

// ---------- cp.async (LDGSTS): in-flight bytes without register cost ----------
__device__ __forceinline__ void cp_async16(uint32_t smem_dst, const void* gmem_src) {
    asm volatile("cp.async.cg.shared.global [%0], [%1], 16;"
                 :: "r"(smem_dst), "l"(gmem_src));
}
#define CP_COMMIT() asm volatile("cp.async.commit_group;" ::: "memory")
#define CP_WAIT1()  asm volatile("cp.async.wait_group 1;"  ::: "memory")

// R10 core (33.5us) with the x path moved to a per-warp cp.async double
// buffer: 2 chunks (4KB) per warp permanently in DRAM flight, held in the
// async queue + SMEM instead of registers. x and W consumed as ulonglong2
// (no packing movs). Same FFMA2 core, same in-warp redux epilogue, one
// block barrier total.
__global__ void __launch_bounds__(TPB, 4)
gating_kernel(const float* __restrict__ x, const float* __restrict__ W,
              const float* __restrict__ b, float* __restrict__ out_w,
              float* __restrict__ out_i, int write_idx)
{
    __shared__ ulonglong2 Ws[NEXP * 256];          // 32 KB
    __shared__ ulonglong2 ring[WARPS][2][TPG * 32]; // 16 KB (2KB/slot/warp)

    const int tid  = threadIdx.x;
    const int lane = tid & 31;
    const int wid  = tid >> 5;

    const int t0 = (blockIdx.x * WARPS + wid) * TPW;
    // byte address of this warp's token block; token tok, chunk c, lane l
    // -> gxb + tok*4096 + c*512 + l*16
    const char* gxb = (const char*)(x + (size_t)t0 * DMODEL);

    const uint32_t rbase =
        (uint32_t)__cvta_generic_to_shared(&ring[wid][0][0]);
    const uint32_t rlane = (uint32_t)lane * 16u;

    // Prologue: chunks 0 and 1 of group 0 in flight before the barrier.
#pragma unroll
    for (int k = 0; k < 2; k++) {
#pragma unroll
        for (int t = 0; t < TPG; t++)
            cp_async16(rbase + (uint32_t)(k & 1) * 2048u + (uint32_t)t * 512u + rlane,
                       gxb + (size_t)t * 4096 + (size_t)k * 512 + lane * 16);
        CP_COMMIT();
    }

    // Stage W: 2048 x 16B / 128 threads = 16 each.
    {
        const ulonglong2* Wv = (const ulonglong2*)W;
#pragma unroll
        for (int i = 0; i < 16; i++)
            Ws[tid + i * TPB] = Wv[tid + i * TPB];
    }
    __syncthreads();   // the only block barrier in the kernel

    const int   elane = (lane >> 2) & 7;      // expert this lane ends up with
    const float bval  = b[elane];

#pragma unroll 1
    for (int g = 0; g < NGRP; g++) {
        ull acc[NEXP][TPG];
#pragma unroll
        for (int e = 0; e < NEXP; e++)
#pragma unroll
            for (int t = 0; t < TPG; t++) acc[e][t] = 0ull;

#pragma unroll
        for (int c = 0; c < 8; c++) {
            const int k = g * 8 + c;

            // Chunk k has landed (only chunk k+1 may still be pending).
            CP_WAIT1();
            ull xlo[TPG], xhi[TPG];
            const ulonglong2* slotp = &ring[wid][k & 1][0];
#pragma unroll
            for (int t = 0; t < TPG; t++) {
                ulonglong2 v = slotp[t * 32 + lane];
                xlo[t] = v.x; xhi[t] = v.y;
            }

            // Refill the just-consumed slot with chunk k+2 (clamped; the
            // tail duplicates hit L2 and are never read).
            {
                int kp = k + 2;
                kp = (kp < NCHUNK - 1) ? kp : (NCHUNK - 1);
                const int gp = kp >> 3, cp = kp & 7;
#pragma unroll
                for (int t = 0; t < TPG; t++)
                    cp_async16(rbase + (uint32_t)(kp & 1) * 2048u + (uint32_t)t * 512u + rlane,
                               gxb + (size_t)(gp * TPG + t) * 4096 + (size_t)cp * 512 + lane * 16);
                CP_COMMIT();
            }

            // W for this chunk, 4 experts at a time (ulonglong2: no packing).
            const ulonglong2* wrow = Ws + c * 32 + lane;
#pragma unroll
            for (int eb = 0; eb < NEXP; eb += 4) {
                ulonglong2 w0 = wrow[(eb + 0) * 256];
                ulonglong2 w1 = wrow[(eb + 1) * 256];
                ulonglong2 w2 = wrow[(eb + 2) * 256];
                ulonglong2 w3 = wrow[(eb + 3) * 256];
#pragma unroll
                for (int t = 0; t < TPG; t++) {
                    acc[eb + 0][t] = ffma2(xhi[t], w0.y, ffma2(xlo[t], w0.x, acc[eb + 0][t]));
                    acc[eb + 1][t] = ffma2(xhi[t], w1.y, ffma2(xlo[t], w1.x, acc[eb + 1][t]));
                    acc[eb + 2][t] = ffma2(xhi[t], w2.y, ffma2(xlo[t], w2.x, acc[eb + 2][t]));
                    acc[eb + 3][t] = ffma2(xhi[t], w3.y, ffma2(xlo[t], w3.x, acc[eb + 3][t]));
                }
            }
        }

        // Finalize + epilogue per token, fully in-warp (R10 verbatim).
#pragma unroll
        for (int t = 0; t < TPG; t++) {
            float s[NEXP];
#pragma unroll
            for (int e = 0; e < NEXP; e++) {
                float lo, hi; unpack2(acc[e][t], lo, hi);
                s[e] = lo + hi;
            }

            // 9-shfl butterfly: experts over lane bits 4,3,2; dims over 1,0.
            const bool h16 = (lane & 16) != 0;
#pragma unroll
            for (int v = 0; v < 4; v++) {
                float d = __shfl_xor_sync(~0u, h16 ? s[v] : s[v + 4], 16);
                s[v] = (h16 ? s[v + 4] : s[v]) + d;
            }
            const bool h8 = (lane & 8) != 0;
#pragma unroll
            for (int v = 0; v < 2; v++) {
                float d = __shfl_xor_sync(~0u, h8 ? s[v] : s[v + 2], 8);
                s[v] = (h8 ? s[v + 2] : s[v]) + d;
            }
            const bool h4 = (lane & 4) != 0;
            {
                float d = __shfl_xor_sync(~0u, h4 ? s[0] : s[1], 4);
                s[0] = (h4 ? s[1] : s[0]) + d;
            }
            float r = s[0];
            r += __shfl_xor_sync(~0u, r, 2);
            r += __shfl_xor_sync(~0u, r, 1);

            // Lane holds the complete logit for expert `elane` (x4 copies).
            const float L = r + bval;
            const unsigned key = fmono(L);
            unsigned k1 = redux_max_u32(key);
            unsigned i1 = redux_min_u32((key == k1) ? (unsigned)elane : 0xFFu);
            unsigned key2 = ((unsigned)elane == i1) ? 0u : key;
            unsigned k2 = redux_max_u32(key2);
            unsigned i2 = redux_min_u32((key2 == k2) ? (unsigned)elane : 0xFFu);

            const float m1 = fmono_inv(k1);
            const float m2 = fmono_inv(k2);
            const float tt  = __expf(m2 - m1);     // m2 <= m1 -> (0,1]
            const float inv = 1.0f / (1.0f + tt);

            const int token = t0 + g * TPG + t;
            if ((lane & 3) == 0) {
                float wgt = ((unsigned)elane == i1) ? inv
                          : (((unsigned)elane == i2) ? tt * inv : 0.0f);
                out_w[token * 8 + elane] = wgt;
            }
            if (lane == t * 8 && write_idx)
                *(float2*)(out_i + token * 2) =
                    make_float2((float)i1, (float)i2);
        }
    }
}

extern "C" void kernel_launch(void* const* d_in, const int* in_sizes, int n_in,
                              void* d_out, int out_size)
{
    const float* x = nullptr; const float* W = nullptr; const float* b = nullptr;
    for (int i = 0; i < n_in; i++) {
        if (in_sizes[i] == NEXP)                b = (const float*)d_in[i];
        else if (in_sizes[i] == NEXP * DMODEL)  W = (const float*)d_in[i];
        else                                    x = (const float*)d_in[i];
    }

    float* ow = (float*)d_out;                       // weights: [B,S,E] f32
    float* oi = ow + (size_t)TOKENS_TOT * NEXP;      // indices (as f32): [B,S,2]
    const int need = TOKENS_TOT * NEXP + TOKENS_TOT * 2;
    const int write_idx = (out_size >= need) ? 1 : 0;

    gating_kernel<<<NBLOCKS, TPB>>>(x, W, b, ow, oi, write_idx);
}